// round 8
// baseline (speedup 1.0000x reference)
#include <cuda_runtime.h>
#include <math.h>

// ---------------- problem constants ----------------
#define Bc    8
#define Pc    16
#define Vc    32
#define Dc    686          // (20-2)*(39-1)+2
#define BPc   128          // B*P
#define NPCc  16384
#define NNSc  8192
#define NOUTc 8192
#define PDc   10976        // P*D

// ---------------- output offsets (tuple order, flattened) ----------------
#define OFF_OVERLAP 0                         // (B,P,P,1)     2048
#define OFF_DIST    2048                      // (B,P,NPC,1)   2097152
#define OFF_X       2099200                   // (B,P,D,3)     263424
#define OFF_SURFD   2362624                   // (B,P,P*D,1)   1404928
#define OFF_SURFP   3767552                   // (B,P*D,3)     263424
#define OFF_NS      4030976                   // (B,P,NNS,1)   1048576
#define OFF_OUT     5079552                   // (B,P,NOUT,1)  1048576
// total = 6128128

// ---------------- persistent device scratch ----------------
__device__ float  g_dirs[Dc * 3];
__device__ float  g_lv[BPc * 96];     // centered verts, [bp][coord(0..2)][v(0..31)]
__device__ float  g_tr[BPc * 3];      // mean (translation)
__device__ float  g_pe[BPc];
__device__ float  g_ipe[BPc];
__device__ float  g_scale[BPc];
__device__ float  g_nrml[BPc * Dc * 3];

// ---------------- core: soft support function ----------------
// z[v] = dot(vert_v, u);  h = (sum clip(max(z,0)/zmax)^pe)^(1/pe)
// NOTE: fmax(fmax(z,0)*k, 1e-30) == fmax(z*k, 1e-30) because k = 1/zmax > 0.
__device__ __forceinline__ float spt_core(
    const float4* __restrict__ sv,
    float pe, float ipe, float ux, float uy, float uz,
    float z[Vc], float& zmax_out)
{
    float zm = -1e30f;
#pragma unroll
    for (int v = 0; v < Vc; v++) {
        float4 w = sv[v];
        float zz = fmaf(w.x, ux, fmaf(w.y, uy, w.z * uz));
        z[v] = zz;
        zm = fmaxf(zm, zz);
    }
    zm = fminf(fmaxf(zm, 1e-30f), 1e30f);
    float k = 1.0f / zm;
    float sum = 0.0f;
#pragma unroll
    for (int v = 0; v < Vc; v++) {
        float t = fmaxf(z[v] * k, 1e-30f);
        sum += __powf(t, pe);
    }
    zmax_out = zm;
    return __powf(sum, ipe);
}

// h_out = clip(h * zmax, -1e30, 1e30)
__device__ __forceinline__ float h_clip(float h, float zm) {
    return fminf(fmaxf(h * zm, -1e30f), 1e30f);
}

// load one bp's vertex set into a float4 shared array (call with tid, then sync)
__device__ __forceinline__ void load_verts(float4* sv, int bp, int tid) {
    if (tid < Vc) {
        sv[tid] = make_float4(g_lv[bp * 96 +  0 + tid],
                              g_lv[bp * 96 + 32 + tid],
                              g_lv[bp * 96 + 64 + tid], 0.0f);
    }
}

// ---------------- kernel: directions (matches numpy linspace/cos in double) ----------------
__global__ void k_dirs() {
    int idx = blockIdx.x * blockDim.x + threadIdx.x;
    if (idx >= Dc) return;
    const double PI = 3.14159265358979323846;
    int i, j;
    if (idx < 684)      { i = idx / 38 + 1; j = idx % 38; }
    else if (idx == 684){ i = 0;  j = 0; }
    else                { i = 19; j = 0; }
    // numpy linspace: arange(n)*step + start, endpoint overwritten exactly
    double th1 = (i == 19) ? (PI / 2.0) : (-PI / 2.0 + (PI / 19.0) * (double)i);
    double th2 = -PI + (PI / 19.0) * (double)j;   // j <= 37, endpoint unused
    double c1 = cos(th1), s1 = sin(th1);
    double c2 = cos(th2), s2 = sin(th2);
    g_dirs[idx * 3 + 0] = (float)(c1 * c2);
    g_dirs[idx * 3 + 1] = (float)(c1 * s2);
    g_dirs[idx * 3 + 2] = (float)s1;
}

// ---------------- kernel: prep (mean, center, pe) ----------------
__global__ void k_prep(const float* __restrict__ verts, const float* __restrict__ smooth) {
    int bp = blockIdx.x;
    int v  = threadIdx.x;   // 32 threads
    float x = verts[(bp * Vc + v) * 3 + 0];
    float y = verts[(bp * Vc + v) * 3 + 1];
    float z = verts[(bp * Vc + v) * 3 + 2];
    float sx = x, sy = y, sz = z;
#pragma unroll
    for (int o = 16; o; o >>= 1) {
        sx += __shfl_xor_sync(0xffffffffu, sx, o);
        sy += __shfl_xor_sync(0xffffffffu, sy, o);
        sz += __shfl_xor_sync(0xffffffffu, sz, o);
    }
    float mx = sx * (1.0f / 32.0f);
    float my = sy * (1.0f / 32.0f);
    float mz = sz * (1.0f / 32.0f);
    g_lv[bp * 96 +  0 + v] = x - mx;
    g_lv[bp * 96 + 32 + v] = y - my;
    g_lv[bp * 96 + 64 + v] = z - mz;
    if (v == 0) {
        g_tr[bp * 3 + 0] = mx;
        g_tr[bp * 3 + 1] = my;
        g_tr[bp * 3 + 2] = mz;
        float pe = smooth[bp];
        g_pe[bp]  = pe;
        g_ipe[bp] = 1.0f / pe;
    }
}

// ---------------- kernel: support along DIRS + x output + scale ----------------
// 256 threads/block; each thread processes 3 directions (686 <= 3*256).
__global__ void __launch_bounds__(256) k_support(float* __restrict__ out) {
    __shared__ float4 sv[Vc];
    __shared__ float sconst[2];        // pe, ipe
    __shared__ float red[8];
    int bp  = blockIdx.x;
    int tid = threadIdx.x;
    load_verts(sv, bp, tid);
    if (tid == 0) { sconst[0] = g_pe[bp]; sconst[1] = g_ipe[bp]; }
    __syncthreads();

    float hmax = -1e30f;
    for (int d = tid; d < Dc; d += 256) {
        float ux = g_dirs[d * 3 + 0];
        float uy = g_dirs[d * 3 + 1];
        float uz = g_dirs[d * 3 + 2];
        float z[Vc], zm;
        float h = spt_core(sv, sconst[0], sconst[1], ux, uy, uz, z, zm);
        hmax = fmaxf(hmax, h_clip(h, zm));
        out[OFF_X + (bp * Dc + d) * 3 + 0] = ux;
        out[OFF_X + (bp * Dc + d) * 3 + 1] = uy;
        out[OFF_X + (bp * Dc + d) * 3 + 2] = uz;
    }
    // block max-reduce -> scale
    float m = hmax;
#pragma unroll
    for (int o = 16; o; o >>= 1) m = fmaxf(m, __shfl_xor_sync(0xffffffffu, m, o));
    if ((tid & 31) == 0) red[tid >> 5] = m;
    __syncthreads();
    if (tid == 0) {
        float mm = red[0];
#pragma unroll
        for (int w = 1; w < 8; w++) mm = fmaxf(mm, red[w]);
        g_scale[bp] = fminf(fmaxf(mm, 1e-10f), 10.0f);
    }
}

// ---------------- kernel: overlap (one block per batch) ----------------
__global__ void __launch_bounds__(256) k_overlap(float* __restrict__ out) {
    __shared__ float4 sv[Pc * Vc];
    __shared__ float st[Pc * 3];
    __shared__ float spe[Pc], sipe[Pc];
    __shared__ float sh[Pc * Pc];
    int b   = blockIdx.x;
    int tid = threadIdx.x;   // 256
    {
        int p = tid >> 4, v2 = (tid & 15) * 2;
        // each thread loads 2 vertices of hull p
        sv[p * Vc + v2 + 0] = make_float4(g_lv[(b * Pc + p) * 96 +  0 + v2],
                                          g_lv[(b * Pc + p) * 96 + 32 + v2],
                                          g_lv[(b * Pc + p) * 96 + 64 + v2], 0.0f);
        sv[p * Vc + v2 + 1] = make_float4(g_lv[(b * Pc + p) * 96 +  0 + v2 + 1],
                                          g_lv[(b * Pc + p) * 96 + 32 + v2 + 1],
                                          g_lv[(b * Pc + p) * 96 + 64 + v2 + 1], 0.0f);
    }
    if (tid < Pc * 3) st[tid] = g_tr[b * Pc * 3 + tid];
    if (tid < Pc) { spe[tid] = g_pe[b * Pc + tid]; sipe[tid] = g_ipe[b * Pc + tid]; }
    __syncthreads();

    int i = tid >> 4, j = tid & 15;
    float dx = st[j * 3 + 0] - st[i * 3 + 0];
    float dy = st[j * 3 + 1] - st[i * 3 + 1];
    float dz = st[j * 3 + 2] - st[i * 3 + 2];
    float ss = dx * dx + dy * dy + dz * dz;
    ss = fminf(fmaxf(ss, 1e-20f), 1e20f);
    float dn = sqrtf(ss);
    float ux, uy, uz;
    if (i == j) { ux = 1.0f; uy = 0.0f; uz = 0.0f; }
    else        { ux = dx / dn; uy = dy / dn; uz = dz / dn; }

    float z[Vc], zm;
    float h = spt_core(&sv[i * Vc], spe[i], sipe[i], ux, uy, uz, z, zm);
    sh[tid] = h_clip(h, zm);
    __syncthreads();

    float sep = dn - sh[i * 16 + j] - sh[j * 16 + i];
    float ov = fmaxf(-sep, 0.0f);
    if (i == j) ov = 0.0f;
    out[OFF_OVERLAP + b * 256 + i * 16 + j] = ov;
}

// ---------------- kernel: surface points + normals ----------------
// grid: (ceil(Dc/256), BPc), 256 threads
__global__ void __launch_bounds__(256) k_surf(float* __restrict__ out) {
    __shared__ float4 sv[Vc];
    __shared__ float sconst[6];   // tx,ty,tz,pe,ipe,scale
    int bp  = blockIdx.y;
    int tid = threadIdx.x;
    load_verts(sv, bp, tid);
    if (tid == 0) {
        sconst[0] = g_tr[bp * 3 + 0];
        sconst[1] = g_tr[bp * 3 + 1];
        sconst[2] = g_tr[bp * 3 + 2];
        sconst[3] = g_pe[bp];
        sconst[4] = g_ipe[bp];
        sconst[5] = g_scale[bp];
    }
    __syncthreads();
    int d = blockIdx.x * 256 + tid;
    if (d >= Dc) return;

    float sc = sconst[5];
    float dxr = g_dirs[d * 3 + 0];
    float dyr = g_dirs[d * 3 + 1];
    float dzr = g_dirs[d * 3 + 2];
    // pts = dirs*scale + trans; local = pts - trans  (replicate reference rounding)
    float px = dxr * sc + sconst[0];
    float py = dyr * sc + sconst[1];
    float pz = dzr * sc + sconst[2];
    float lx = px - sconst[0];
    float ly = py - sconst[1];
    float lz = pz - sconst[2];
    float ss = lx * lx + ly * ly + lz * lz;
    ss = fminf(fmaxf(ss, 1e-40f), 1e40f);
    float nrm = sqrtf(ss);
    float ux = lx / nrm, uy = ly / nrm, uz = lz / nrm;

    float pe = sconst[3];
    float z[Vc], zm;
    float h = spt_core(sv, pe, sconst[4], ux, uy, uz, z, zm);
    float s = fminf(fmaxf(h, 1e-30f), 1e30f);
    float rins = 1.0f / s;
    float k = 1.0f / zm;
    float pem1 = pe - 1.0f;
    float ax = 0.0f, ay = 0.0f, az = 0.0f;
#pragma unroll
    for (int v = 0; v < Vc; v++) {
        float t = fmaxf(z[v] * k, 1e-30f);
        float r = t * rins;
        float dh = fminf(fmaxf(__powf(r, pem1), 1e-30f), 1e30f);
        float4 w = sv[v];
        ax = fmaf(dh, w.x, ax);
        ay = fmaf(dh, w.y, ay);
        az = fmaf(dh, w.z, az);
    }
    int base = OFF_SURFP + (bp * Dc + d) * 3;
    out[base + 0] = ax + sconst[0];
    out[base + 1] = ay + sconst[1];
    out[base + 2] = az + sconst[2];
    g_nrml[(bp * Dc + d) * 3 + 0] = ux;
    g_nrml[(bp * Dc + d) * 3 + 1] = uy;
    g_nrml[(bp * Dc + d) * 3 + 2] = uz;
}

// ---------------- kernel: generic point-distance ----------------
__global__ void __launch_bounds__(256) k_dist(const float* __restrict__ pts, int N,
                                              float* __restrict__ out, int outoff) {
    __shared__ float4 sv[Vc];
    __shared__ float sconst[5];   // tx,ty,tz,pe,ipe
    int bp  = blockIdx.y;
    int tid = threadIdx.x;
    load_verts(sv, bp, tid);
    if (tid == 0) {
        sconst[0] = g_tr[bp * 3 + 0];
        sconst[1] = g_tr[bp * 3 + 1];
        sconst[2] = g_tr[bp * 3 + 2];
        sconst[3] = g_pe[bp];
        sconst[4] = g_ipe[bp];
    }
    __syncthreads();
    int q = blockIdx.x * blockDim.x + tid;
    if (q >= N) return;
    int b = bp >> 4;
    float px = pts[(b * N + q) * 3 + 0];
    float py = pts[(b * N + q) * 3 + 1];
    float pz = pts[(b * N + q) * 3 + 2];
    float lx = px - sconst[0];
    float ly = py - sconst[1];
    float lz = pz - sconst[2];
    float ss = lx * lx + ly * ly + lz * lz;
    ss = fminf(fmaxf(ss, 1e-40f), 1e40f);
    float nrm = sqrtf(ss);
    float ux = lx / nrm, uy = ly / nrm, uz = lz / nrm;
    float z[Vc], zm;
    float h = spt_core(sv, sconst[3], sconst[4], ux, uy, uz, z, zm);
    out[outoff + bp * N + q] = nrm - h_clip(h, zm);
}

// ---------------- kernel: surf_distance (with normal filter + diagonal) ----------------
__global__ void __launch_bounds__(256) k_sdist(const float* __restrict__ outro,
                                               float* __restrict__ out) {
    __shared__ float4 sv[Vc];
    __shared__ float st[Pc * 3];
    __shared__ float sconst[5];
    int bp  = blockIdx.y;
    int b   = bp >> 4;
    int i   = bp & 15;
    int tid = threadIdx.x;
    load_verts(sv, bp, tid);
    if (tid < Pc * 3) st[tid] = g_tr[b * Pc * 3 + tid];
    if (tid == 0) {
        sconst[0] = g_tr[bp * 3 + 0];
        sconst[1] = g_tr[bp * 3 + 1];
        sconst[2] = g_tr[bp * 3 + 2];
        sconst[3] = g_pe[bp];
        sconst[4] = g_ipe[bp];
    }
    __syncthreads();
    int n = blockIdx.x * blockDim.x + tid;
    if (n >= PDc) return;
    int j  = n / Dc;
    int dd = n - j * Dc;

    float res = 100.0f;
    bool compute = (i != j);
    if (compute) {
        float nx = g_nrml[(bp * Dc + dd) * 3 + 0];
        float ny = g_nrml[(bp * Dc + dd) * 3 + 1];
        float nz = g_nrml[(bp * Dc + dd) * 3 + 2];
        float ltx = st[j * 3 + 0] - sconst[0];
        float lty = st[j * 3 + 1] - sconst[1];
        float ltz = st[j * 3 + 2] - sconst[2];
        float nf = ltx * nx + lty * ny + ltz * nz;
        compute = !(nf < 0.0f);
    }
    if (compute) {
        float px = outro[OFF_SURFP + (b * PDc + n) * 3 + 0];
        float py = outro[OFF_SURFP + (b * PDc + n) * 3 + 1];
        float pz = outro[OFF_SURFP + (b * PDc + n) * 3 + 2];
        float lx = px - sconst[0];
        float ly = py - sconst[1];
        float lz = pz - sconst[2];
        float ss = lx * lx + ly * ly + lz * lz;
        ss = fminf(fmaxf(ss, 1e-40f), 1e40f);
        float nrm = sqrtf(ss);
        float ux = lx / nrm, uy = ly / nrm, uz = lz / nrm;
        float z[Vc], zm;
        float h = spt_core(sv, sconst[3], sconst[4], ux, uy, uz, z, zm);
        res = nrm - h_clip(h, zm);
    }
    out[OFF_SURFD + bp * PDc + n] = res;
}

// ---------------- launch ----------------
extern "C" void kernel_launch(void* const* d_in, const int* in_sizes, int n_in,
                              void* d_out, int out_size) {
    const float* verts  = (const float*)d_in[0];   // (B,P,V,3)
    const float* smooth = (const float*)d_in[1];   // (B,P)
    const float* pc     = (const float*)d_in[2];   // (B,NPC,3)
    const float* ns     = (const float*)d_in[3];   // (B,NNS,3)
    const float* op     = (const float*)d_in[4];   // (B,NOUT,3)
    float* out = (float*)d_out;

    k_dirs<<<3, 256>>>();
    k_prep<<<BPc, 32>>>(verts, smooth);
    k_support<<<BPc, 256>>>(out);
    k_overlap<<<Bc, 256>>>(out);
    k_surf<<<dim3((Dc + 255) / 256, BPc), 256>>>(out);
    k_dist<<<dim3(NPCc / 256, BPc), 256>>>(pc, NPCc, out, OFF_DIST);
    k_sdist<<<dim3((PDc + 255) / 256, BPc), 256>>>(out, out);
    k_dist<<<dim3(NNSc / 256, BPc), 256>>>(ns, NNSc, out, OFF_NS);
    k_dist<<<dim3(NOUTc / 256, BPc), 256>>>(op, NOUTc, out, OFF_OUT);
    (void)in_sizes; (void)n_in; (void)out_size;
}

// round 11
// speedup vs baseline: 1.7178x; 1.7178x over previous
#include <cuda_runtime.h>
#include <math.h>

// ---------------- problem constants ----------------
#define Bc    8
#define Pc    16
#define Vc    32
#define Dc    686          // (20-2)*(39-1)+2
#define BPc   128          // B*P
#define NPCc  16384
#define NNSc  8192
#define NOUTc 8192
#define PDc   10976        // P*D

// ---------------- output offsets (tuple order, flattened) ----------------
#define OFF_OVERLAP 0                         // (B,P,P,1)     2048
#define OFF_DIST    2048                      // (B,P,NPC,1)   2097152
#define OFF_X       2099200                   // (B,P,D,3)     263424
#define OFF_SURFD   2362624                   // (B,P,P*D,1)   1404928
#define OFF_SURFP   3767552                   // (B,P*D,3)     263424
#define OFF_NS      4030976                   // (B,P,NNS,1)   1048576
#define OFF_OUT     5079552                   // (B,P,NOUT,1)  1048576
// total = 6128128

// ---------------- persistent device scratch ----------------
__device__ float  g_dirs[Dc * 3];
__device__ float  g_lv[BPc * 96];     // centered verts, [bp][coord(0..2)][v(0..31)]
__device__ float  g_tr[BPc * 3];      // mean (translation)
__device__ float  g_pe[BPc];
__device__ float  g_ipe[BPc];
__device__ float  g_nrml[BPc * Dc * 3];

// ---------------- fast approx helpers (single MUFU each) ----------------
__device__ __forceinline__ float f_rcp(float x)   { float r; asm("rcp.approx.f32 %0, %1;"   : "=f"(r) : "f"(x)); return r; }
__device__ __forceinline__ float f_rsqrt(float x) { float r; asm("rsqrt.approx.f32 %0, %1;" : "=f"(r) : "f"(x)); return r; }

// ---------------- core: soft support function ----------------
// z[v] = dot(vert_v, u);  h = (sum clip(max(z,0)/zmax)^pe)^(1/pe)
// NOTE: fmax(fmax(z,0)*k, 1e-30) == fmax(z*k, 1e-30) because k = 1/zmax > 0.
__device__ __forceinline__ float spt_core(
    const float4* __restrict__ sv,
    float pe, float ipe, float ux, float uy, float uz,
    float z[Vc], float& zmax_out)
{
    float zm = -1e30f;
#pragma unroll
    for (int v = 0; v < Vc; v++) {
        float4 w = sv[v];
        float zz = fmaf(w.x, ux, fmaf(w.y, uy, w.z * uz));
        z[v] = zz;
        zm = fmaxf(zm, zz);
    }
    zm = fminf(fmaxf(zm, 1e-30f), 1e30f);
    float k = f_rcp(zm);
    float sum = 0.0f;
#pragma unroll
    for (int v = 0; v < Vc; v++) {
        float t = fmaxf(z[v] * k, 1e-30f);
        sum += __powf(t, pe);
    }
    zmax_out = zm;
    return __powf(sum, ipe);
}

// h_out = clip(h * zmax, -1e30, 1e30)
__device__ __forceinline__ float h_clip(float h, float zm) {
    return fminf(fmaxf(h * zm, -1e30f), 1e30f);
}

// load one bp's vertex set into a float4 shared array (call with tid, then sync)
__device__ __forceinline__ void load_verts(float4* sv, int bp, int tid) {
    if (tid < Vc) {
        sv[tid] = make_float4(g_lv[bp * 96 +  0 + tid],
                              g_lv[bp * 96 + 32 + tid],
                              g_lv[bp * 96 + 64 + tid], 0.0f);
    }
}

// ---------------- kernel: init = dirs + prep fused ----------------
// grid: 19 blocks x 256.  x<3: directions.  x>=3: prep, warp w handles bp=(x-3)*8+w.
__global__ void __launch_bounds__(256) k_init(const float* __restrict__ verts,
                                              const float* __restrict__ smooth) {
    int tid = threadIdx.x;
    if (blockIdx.x < 3) {
        int idx = blockIdx.x * 256 + tid;
        if (idx >= Dc) return;
        const double PI = 3.14159265358979323846;
        int i, j;
        if (idx < 684)      { i = idx / 38 + 1; j = idx % 38; }
        else if (idx == 684){ i = 0;  j = 0; }
        else                { i = 19; j = 0; }
        double th1 = (i == 19) ? (PI / 2.0) : (-PI / 2.0 + (PI / 19.0) * (double)i);
        double th2 = -PI + (PI / 19.0) * (double)j;
        double c1 = cos(th1), s1 = sin(th1);
        double c2 = cos(th2), s2 = sin(th2);
        g_dirs[idx * 3 + 0] = (float)(c1 * c2);
        g_dirs[idx * 3 + 1] = (float)(c1 * s2);
        g_dirs[idx * 3 + 2] = (float)s1;
        return;
    }
    int bp = (blockIdx.x - 3) * 8 + (tid >> 5);
    int v  = tid & 31;
    float x = verts[(bp * Vc + v) * 3 + 0];
    float y = verts[(bp * Vc + v) * 3 + 1];
    float z = verts[(bp * Vc + v) * 3 + 2];
    float sx = x, sy = y, sz = z;
#pragma unroll
    for (int o = 16; o; o >>= 1) {
        sx += __shfl_xor_sync(0xffffffffu, sx, o);
        sy += __shfl_xor_sync(0xffffffffu, sy, o);
        sz += __shfl_xor_sync(0xffffffffu, sz, o);
    }
    float mx = sx * (1.0f / 32.0f);
    float my = sy * (1.0f / 32.0f);
    float mz = sz * (1.0f / 32.0f);
    g_lv[bp * 96 +  0 + v] = x - mx;
    g_lv[bp * 96 + 32 + v] = y - my;
    g_lv[bp * 96 + 64 + v] = z - mz;
    if (v == 0) {
        g_tr[bp * 3 + 0] = mx;
        g_tr[bp * 3 + 1] = my;
        g_tr[bp * 3 + 2] = mz;
        float pe = smooth[bp];
        g_pe[bp]  = pe;
        g_ipe[bp] = 1.0f / pe;   // host-visible semantics: exact divide, once per bp
    }
}

// ---------------- kernel: overlap (one block per batch) ----------------
__global__ void __launch_bounds__(256) k_overlap(float* __restrict__ out) {
    __shared__ float4 sv[Pc * Vc];
    __shared__ float st[Pc * 3];
    __shared__ float spe[Pc], sipe[Pc];
    __shared__ float sh[Pc * Pc];
    int b   = blockIdx.x;
    int tid = threadIdx.x;   // 256
    {
        int p = tid >> 4, v2 = (tid & 15) * 2;
        sv[p * Vc + v2 + 0] = make_float4(g_lv[(b * Pc + p) * 96 +  0 + v2],
                                          g_lv[(b * Pc + p) * 96 + 32 + v2],
                                          g_lv[(b * Pc + p) * 96 + 64 + v2], 0.0f);
        sv[p * Vc + v2 + 1] = make_float4(g_lv[(b * Pc + p) * 96 +  0 + v2 + 1],
                                          g_lv[(b * Pc + p) * 96 + 32 + v2 + 1],
                                          g_lv[(b * Pc + p) * 96 + 64 + v2 + 1], 0.0f);
    }
    if (tid < Pc * 3) st[tid] = g_tr[b * Pc * 3 + tid];
    if (tid < Pc) { spe[tid] = g_pe[b * Pc + tid]; sipe[tid] = g_ipe[b * Pc + tid]; }
    __syncthreads();

    int i = tid >> 4, j = tid & 15;
    float dx = st[j * 3 + 0] - st[i * 3 + 0];
    float dy = st[j * 3 + 1] - st[i * 3 + 1];
    float dz = st[j * 3 + 2] - st[i * 3 + 2];
    float ss = dx * dx + dy * dy + dz * dz;
    ss = fminf(fmaxf(ss, 1e-20f), 1e20f);
    float rinv = f_rsqrt(ss);
    float dn = ss * rinv;
    float ux, uy, uz;
    if (i == j) { ux = 1.0f; uy = 0.0f; uz = 0.0f; }
    else        { ux = dx * rinv; uy = dy * rinv; uz = dz * rinv; }

    float z[Vc], zm;
    float h = spt_core(&sv[i * Vc], spe[i], sipe[i], ux, uy, uz, z, zm);
    sh[tid] = h_clip(h, zm);
    __syncthreads();

    float sep = dn - sh[i * 16 + j] - sh[j * 16 + i];
    float ov = fmaxf(-sep, 0.0f);
    if (i == j) ov = 0.0f;
    out[OFF_OVERLAP + b * 256 + i * 16 + j] = ov;
}

// ---------------- kernel: fused support (x, scale) + surface points/normals ----------------
// one block per bp; 256 threads; each thread covers d, d+256, d+512.
__global__ void __launch_bounds__(256) k_supsurf(float* __restrict__ out) {
    __shared__ float4 sv[Vc];
    __shared__ float sconst[5];   // tx,ty,tz,pe,ipe
    __shared__ float red[8];
    __shared__ float s_scale;
    int bp  = blockIdx.x;
    int tid = threadIdx.x;
    load_verts(sv, bp, tid);
    if (tid == 0) {
        sconst[0] = g_tr[bp * 3 + 0];
        sconst[1] = g_tr[bp * 3 + 1];
        sconst[2] = g_tr[bp * 3 + 2];
        sconst[3] = g_pe[bp];
        sconst[4] = g_ipe[bp];
    }
    __syncthreads();

    // ---- phase 1: support along DIRS, write x, reduce scale ----
    float hmax = -1e30f;
    for (int d = tid; d < Dc; d += 256) {
        float ux = g_dirs[d * 3 + 0];
        float uy = g_dirs[d * 3 + 1];
        float uz = g_dirs[d * 3 + 2];
        float z[Vc], zm;
        float h = spt_core(sv, sconst[3], sconst[4], ux, uy, uz, z, zm);
        hmax = fmaxf(hmax, h_clip(h, zm));
        out[OFF_X + (bp * Dc + d) * 3 + 0] = ux;
        out[OFF_X + (bp * Dc + d) * 3 + 1] = uy;
        out[OFF_X + (bp * Dc + d) * 3 + 2] = uz;
    }
    float m = hmax;
#pragma unroll
    for (int o = 16; o; o >>= 1) m = fmaxf(m, __shfl_xor_sync(0xffffffffu, m, o));
    if ((tid & 31) == 0) red[tid >> 5] = m;
    __syncthreads();
    if (tid == 0) {
        float mm = red[0];
#pragma unroll
        for (int w = 1; w < 8; w++) mm = fmaxf(mm, red[w]);
        s_scale = fminf(fmaxf(mm, 1e-10f), 10.0f);
    }
    __syncthreads();

    // ---- phase 2: surface points + normals ----
    float sc  = s_scale;
    float pe  = sconst[3];
    float ipe = sconst[4];
    for (int d = tid; d < Dc; d += 256) {
        float dxr = g_dirs[d * 3 + 0];
        float dyr = g_dirs[d * 3 + 1];
        float dzr = g_dirs[d * 3 + 2];
        // pts = dirs*scale + trans; local = pts - trans  (replicate reference rounding)
        float px = dxr * sc + sconst[0];
        float py = dyr * sc + sconst[1];
        float pz = dzr * sc + sconst[2];
        float lx = px - sconst[0];
        float ly = py - sconst[1];
        float lz = pz - sconst[2];
        float ss = lx * lx + ly * ly + lz * lz;
        ss = fminf(fmaxf(ss, 1e-40f), 1e40f);
        float rinv = f_rsqrt(ss);
        float ux = lx * rinv, uy = ly * rinv, uz = lz * rinv;

        float z[Vc], zm;
        float h = spt_core(sv, pe, ipe, ux, uy, uz, z, zm);
        float s = fminf(fmaxf(h, 1e-30f), 1e30f);
        float rins = f_rcp(s);
        float k = f_rcp(zm);
        float pem1 = pe - 1.0f;
        float ax = 0.0f, ay = 0.0f, az = 0.0f;
#pragma unroll
        for (int v = 0; v < Vc; v++) {
            float t = fmaxf(z[v] * k, 1e-30f);
            float r = t * rins;
            float dh = fminf(fmaxf(__powf(r, pem1), 1e-30f), 1e30f);
            float4 w = sv[v];
            ax = fmaf(dh, w.x, ax);
            ay = fmaf(dh, w.y, ay);
            az = fmaf(dh, w.z, az);
        }
        int base = OFF_SURFP + (bp * Dc + d) * 3;
        out[base + 0] = ax + sconst[0];
        out[base + 1] = ay + sconst[1];
        out[base + 2] = az + sconst[2];
        g_nrml[(bp * Dc + d) * 3 + 0] = ux;
        g_nrml[(bp * Dc + d) * 3 + 1] = uy;
        g_nrml[(bp * Dc + d) * 3 + 2] = uz;
    }
}

// ---------------- mega kernel: 3x point-distance + surf_distance ----------------
// grid: (171, BPc).  x in [0,64): pc; [64,96): ns; [96,128): out; [128,171): sdist.
__global__ void __launch_bounds__(256) k_mega(const float* __restrict__ pc,
                                              const float* __restrict__ ns,
                                              const float* __restrict__ op,
                                              float* __restrict__ out) {
    __shared__ float4 sv[Vc];
    __shared__ float st[Pc * 3];
    __shared__ float sconst[5];   // tx,ty,tz,pe,ipe
    int bp  = blockIdx.y;
    int b   = bp >> 4;
    int tid = threadIdx.x;
    load_verts(sv, bp, tid);
    if (tid < Pc * 3) st[tid] = g_tr[b * Pc * 3 + tid];
    if (tid == 0) {
        sconst[0] = g_tr[bp * 3 + 0];
        sconst[1] = g_tr[bp * 3 + 1];
        sconst[2] = g_tr[bp * 3 + 2];
        sconst[3] = g_pe[bp];
        sconst[4] = g_ipe[bp];
    }
    __syncthreads();

    int bx = blockIdx.x;
    if (bx < 128) {
        // ---- point-distance segments ----
        const float* pts; int N, outoff, q;
        if (bx < 64)       { pts = pc; N = NPCc;  outoff = OFF_DIST; q = bx * 256 + tid; }
        else if (bx < 96)  { pts = ns; N = NNSc;  outoff = OFF_NS;   q = (bx - 64) * 256 + tid; }
        else               { pts = op; N = NOUTc; outoff = OFF_OUT;  q = (bx - 96) * 256 + tid; }
        float px = pts[(b * N + q) * 3 + 0];
        float py = pts[(b * N + q) * 3 + 1];
        float pz = pts[(b * N + q) * 3 + 2];
        float lx = px - sconst[0];
        float ly = py - sconst[1];
        float lz = pz - sconst[2];
        float ss = lx * lx + ly * ly + lz * lz;
        ss = fminf(fmaxf(ss, 1e-40f), 1e40f);
        float rinv = f_rsqrt(ss);
        float nrm = ss * rinv;
        float ux = lx * rinv, uy = ly * rinv, uz = lz * rinv;
        float z[Vc], zm;
        float h = spt_core(sv, sconst[3], sconst[4], ux, uy, uz, z, zm);
        out[outoff + bp * N + q] = nrm - h_clip(h, zm);
        return;
    }

    // ---- surf_distance segment (with normal filter + diagonal) ----
    int n = (bx - 128) * 256 + tid;
    if (n >= PDc) return;
    int i  = bp & 15;
    int j  = n / Dc;
    int dd = n - j * Dc;

    float res = 100.0f;
    bool compute = (i != j);
    if (compute) {
        float nx = g_nrml[(bp * Dc + dd) * 3 + 0];
        float ny = g_nrml[(bp * Dc + dd) * 3 + 1];
        float nz = g_nrml[(bp * Dc + dd) * 3 + 2];
        float ltx = st[j * 3 + 0] - sconst[0];
        float lty = st[j * 3 + 1] - sconst[1];
        float ltz = st[j * 3 + 2] - sconst[2];
        float nf = ltx * nx + lty * ny + ltz * nz;
        compute = !(nf < 0.0f);
    }
    if (compute) {
        float px = out[OFF_SURFP + (b * PDc + n) * 3 + 0];
        float py = out[OFF_SURFP + (b * PDc + n) * 3 + 1];
        float pz = out[OFF_SURFP + (b * PDc + n) * 3 + 2];
        float lx = px - sconst[0];
        float ly = py - sconst[1];
        float lz = pz - sconst[2];
        float ss = lx * lx + ly * ly + lz * lz;
        ss = fminf(fmaxf(ss, 1e-40f), 1e40f);
        float rinv = f_rsqrt(ss);
        float nrm = ss * rinv;
        float ux = lx * rinv, uy = ly * rinv, uz = lz * rinv;
        float z[Vc], zm;
        float h = spt_core(sv, sconst[3], sconst[4], ux, uy, uz, z, zm);
        res = nrm - h_clip(h, zm);
    }
    out[OFF_SURFD + bp * PDc + n] = res;
}

// ---------------- launch ----------------
extern "C" void kernel_launch(void* const* d_in, const int* in_sizes, int n_in,
                              void* d_out, int out_size) {
    const float* verts  = (const float*)d_in[0];   // (B,P,V,3)
    const float* smooth = (const float*)d_in[1];   // (B,P)
    const float* pc     = (const float*)d_in[2];   // (B,NPC,3)
    const float* ns     = (const float*)d_in[3];   // (B,NNS,3)
    const float* op     = (const float*)d_in[4];   // (B,NOUT,3)
    float* out = (float*)d_out;

    k_init<<<19, 256>>>(verts, smooth);
    k_overlap<<<Bc, 256>>>(out);
    k_supsurf<<<BPc, 256>>>(out);
    k_mega<<<dim3(171, BPc), 256>>>(pc, ns, op, out);
    (void)in_sizes; (void)n_in; (void)out_size;
}

// round 16
// speedup vs baseline: 2.0728x; 1.2066x over previous
#include <cuda_runtime.h>
#include <math.h>

// ---------------- problem constants ----------------
#define Bc    8
#define Pc    16
#define Vc    32
#define Dc    686          // (20-2)*(39-1)+2
#define BPc   128          // B*P
#define NPCc  16384
#define NNSc  8192
#define NOUTc 8192
#define PDc   10976        // P*D

// ---------------- output offsets (tuple order, flattened) ----------------
#define OFF_OVERLAP 0                         // (B,P,P,1)     2048
#define OFF_DIST    2048                      // (B,P,NPC,1)   2097152
#define OFF_X       2099200                   // (B,P,D,3)     263424
#define OFF_SURFD   2362624                   // (B,P,P*D,1)   1404928
#define OFF_SURFP   3767552                   // (B,P*D,3)     263424
#define OFF_NS      4030976                   // (B,P,NNS,1)   1048576
#define OFF_OUT     5079552                   // (B,P,NOUT,1)  1048576
// total = 6128128

// ---------------- persistent device scratch ----------------
__device__ float  g_dirs[Dc * 3];
__device__ float  g_lv[BPc * 96];     // centered verts, [bp][coord(0..2)][v(0..31)]
__device__ float  g_tr[BPc * 3];      // mean (translation)
__device__ float  g_pe[BPc];
__device__ float  g_ipe[BPc];
__device__ float  g_nrml[BPc * Dc * 3];

// ---------------- fast approx helpers (single MUFU each) ----------------
__device__ __forceinline__ float f_rsqrt(float x) { float r; asm("rsqrt.approx.f32 %0, %1;" : "=f"(r) : "f"(x)); return r; }
__device__ __forceinline__ float f_lg2(float x)   { float r; asm("lg2.approx.f32 %0, %1;"   : "=f"(r) : "f"(x)); return r; }
__device__ __forceinline__ float f_ex2(float x)   { float r; asm("ex2.approx.f32 %0, %1;"   : "=f"(r) : "f"(x)); return r; }

// ---------------- core: UNNORMALIZED soft support ----------------
// Reference computes h_out = zmax * (sum clip(max(z,0)/zmax)^pe)^(1/pe).
// The zmax normalization cancels algebraically:
//   h_out = (sum max(z, 1e-30*zmax)^pe)^(1/pe)
// and for z <= tiny the contribution underflows to 0 in fp32 either way
// (pe >= 2.5 so (1e-30)^pe -> 0). So: one fused loop, no z[] array, no zmax.
__device__ __forceinline__ float h_support(
    const float4* __restrict__ sv, float pe, float ipe,
    float ux, float uy, float uz)
{
    float sum = 0.0f;
#pragma unroll
    for (int v = 0; v < Vc; v++) {
        float4 w = sv[v];
        float z  = fmaf(w.x, ux, fmaf(w.y, uy, w.z * uz));
        float lz = f_lg2(fmaxf(z, 1e-35f));
        sum += f_ex2(pe * lz);
    }
    // sum == 0 -> lg2 = -inf -> ex2 -> 0 (matches reference h=0)
    return f_ex2(ipe * f_lg2(sum));
}

// load one bp's vertex set into a float4 shared array (call with tid, then sync)
__device__ __forceinline__ void load_verts(float4* sv, int bp, int tid) {
    if (tid < Vc) {
        sv[tid] = make_float4(g_lv[bp * 96 +  0 + tid],
                              g_lv[bp * 96 + 32 + tid],
                              g_lv[bp * 96 + 64 + tid], 0.0f);
    }
}

// ---------------- kernel: init = dirs + prep fused ----------------
// grid: 19 blocks x 256.  x<3: directions.  x>=3: prep, warp w handles bp=(x-3)*8+w.
__global__ void __launch_bounds__(256) k_init(const float* __restrict__ verts,
                                              const float* __restrict__ smooth) {
    int tid = threadIdx.x;
    if (blockIdx.x < 3) {
        int idx = blockIdx.x * 256 + tid;
        if (idx >= Dc) return;
        const double PI = 3.14159265358979323846;
        int i, j;
        if (idx < 684)      { i = idx / 38 + 1; j = idx % 38; }
        else if (idx == 684){ i = 0;  j = 0; }
        else                { i = 19; j = 0; }
        double th1 = (i == 19) ? (PI / 2.0) : (-PI / 2.0 + (PI / 19.0) * (double)i);
        double th2 = -PI + (PI / 19.0) * (double)j;
        double c1 = cos(th1), s1 = sin(th1);
        double c2 = cos(th2), s2 = sin(th2);
        g_dirs[idx * 3 + 0] = (float)(c1 * c2);
        g_dirs[idx * 3 + 1] = (float)(c1 * s2);
        g_dirs[idx * 3 + 2] = (float)s1;
        return;
    }
    int bp = (blockIdx.x - 3) * 8 + (tid >> 5);
    int v  = tid & 31;
    float x = verts[(bp * Vc + v) * 3 + 0];
    float y = verts[(bp * Vc + v) * 3 + 1];
    float z = verts[(bp * Vc + v) * 3 + 2];
    float sx = x, sy = y, sz = z;
#pragma unroll
    for (int o = 16; o; o >>= 1) {
        sx += __shfl_xor_sync(0xffffffffu, sx, o);
        sy += __shfl_xor_sync(0xffffffffu, sy, o);
        sz += __shfl_xor_sync(0xffffffffu, sz, o);
    }
    float mx = sx * (1.0f / 32.0f);
    float my = sy * (1.0f / 32.0f);
    float mz = sz * (1.0f / 32.0f);
    g_lv[bp * 96 +  0 + v] = x - mx;
    g_lv[bp * 96 + 32 + v] = y - my;
    g_lv[bp * 96 + 64 + v] = z - mz;
    if (v == 0) {
        g_tr[bp * 3 + 0] = mx;
        g_tr[bp * 3 + 1] = my;
        g_tr[bp * 3 + 2] = mz;
        float pe = smooth[bp];
        g_pe[bp]  = pe;
        g_ipe[bp] = 1.0f / pe;
    }
}

// ---------------- kernel: mid = overlap + (support/x/scale + surf) fused ----------------
// grid: (Bc + BPc) blocks x 256.  x<Bc: overlap for batch x.  else: supsurf for bp=x-Bc.
__global__ void __launch_bounds__(256) k_mid(float* __restrict__ out) {
    int tid = threadIdx.x;

    if (blockIdx.x < Bc) {
        // ======== overlap (one block per batch) ========
        __shared__ float4 svb[Pc * Vc];
        __shared__ float st[Pc * 3];
        __shared__ float spe[Pc], sipe[Pc];
        __shared__ float sh[Pc * Pc];
        int b = blockIdx.x;
        {
            int p = tid >> 4, v2 = (tid & 15) * 2;
            svb[p * Vc + v2 + 0] = make_float4(g_lv[(b * Pc + p) * 96 +  0 + v2],
                                               g_lv[(b * Pc + p) * 96 + 32 + v2],
                                               g_lv[(b * Pc + p) * 96 + 64 + v2], 0.0f);
            svb[p * Vc + v2 + 1] = make_float4(g_lv[(b * Pc + p) * 96 +  0 + v2 + 1],
                                               g_lv[(b * Pc + p) * 96 + 32 + v2 + 1],
                                               g_lv[(b * Pc + p) * 96 + 64 + v2 + 1], 0.0f);
        }
        if (tid < Pc * 3) st[tid] = g_tr[b * Pc * 3 + tid];
        if (tid < Pc) { spe[tid] = g_pe[b * Pc + tid]; sipe[tid] = g_ipe[b * Pc + tid]; }
        __syncthreads();

        int i = tid >> 4, j = tid & 15;
        float dx = st[j * 3 + 0] - st[i * 3 + 0];
        float dy = st[j * 3 + 1] - st[i * 3 + 1];
        float dz = st[j * 3 + 2] - st[i * 3 + 2];
        float ss = dx * dx + dy * dy + dz * dz;
        ss = fminf(fmaxf(ss, 1e-20f), 1e20f);
        float rinv = f_rsqrt(ss);
        float dn = ss * rinv;
        float ux, uy, uz;
        if (i == j) { ux = 1.0f; uy = 0.0f; uz = 0.0f; }
        else        { ux = dx * rinv; uy = dy * rinv; uz = dz * rinv; }

        sh[tid] = h_support(&svb[i * Vc], spe[i], sipe[i], ux, uy, uz);
        __syncthreads();

        float sep = dn - sh[i * 16 + j] - sh[j * 16 + i];
        float ov = fmaxf(-sep, 0.0f);
        if (i == j) ov = 0.0f;
        out[OFF_OVERLAP + b * 256 + i * 16 + j] = ov;
        return;
    }

    // ======== support (x, scale) + surface points/normals (one block per bp) ========
    __shared__ float4 sv[Vc];
    __shared__ float sconst[5];   // tx,ty,tz,pe,ipe
    __shared__ float red[8];
    __shared__ float s_scale;
    int bp = blockIdx.x - Bc;
    load_verts(sv, bp, tid);
    if (tid == 0) {
        sconst[0] = g_tr[bp * 3 + 0];
        sconst[1] = g_tr[bp * 3 + 1];
        sconst[2] = g_tr[bp * 3 + 2];
        sconst[3] = g_pe[bp];
        sconst[4] = g_ipe[bp];
    }
    __syncthreads();

    float pe  = sconst[3];
    float ipe = sconst[4];

    // ---- phase 1: support along DIRS, write x, reduce scale ----
    float hmax = -1e30f;
    for (int d = tid; d < Dc; d += 256) {
        float ux = g_dirs[d * 3 + 0];
        float uy = g_dirs[d * 3 + 1];
        float uz = g_dirs[d * 3 + 2];
        hmax = fmaxf(hmax, h_support(sv, pe, ipe, ux, uy, uz));
        out[OFF_X + (bp * Dc + d) * 3 + 0] = ux;
        out[OFF_X + (bp * Dc + d) * 3 + 1] = uy;
        out[OFF_X + (bp * Dc + d) * 3 + 2] = uz;
    }
    float m = hmax;
#pragma unroll
    for (int o = 16; o; o >>= 1) m = fmaxf(m, __shfl_xor_sync(0xffffffffu, m, o));
    if ((tid & 31) == 0) red[tid >> 5] = m;
    __syncthreads();
    if (tid == 0) {
        float mm = red[0];
#pragma unroll
        for (int w = 1; w < 8; w++) mm = fmaxf(mm, red[w]);
        s_scale = fminf(fmaxf(mm, 1e-10f), 10.0f);
    }
    __syncthreads();

    // ---- phase 2: surface points + normals ----
    // dhdz = clip((z*k/h)^(pe-1)) = clip((z/h_out)^(pe-1))  (normalization cancels)
    float sc = s_scale;
    float pem1 = pe - 1.0f;
    for (int d = tid; d < Dc; d += 256) {
        float dxr = g_dirs[d * 3 + 0];
        float dyr = g_dirs[d * 3 + 1];
        float dzr = g_dirs[d * 3 + 2];
        // pts = dirs*scale + trans; local = pts - trans (replicate reference rounding)
        float px = dxr * sc + sconst[0];
        float py = dyr * sc + sconst[1];
        float pz = dzr * sc + sconst[2];
        float lx = px - sconst[0];
        float ly = py - sconst[1];
        float lz = pz - sconst[2];
        float ss = lx * lx + ly * ly + lz * lz;
        ss = fminf(fmaxf(ss, 1e-40f), 1e40f);
        float rinv = f_rsqrt(ss);
        float ux = lx * rinv, uy = ly * rinv, uz = lz * rinv;

        float lzv[Vc];
        float sum = 0.0f;
#pragma unroll
        for (int v = 0; v < Vc; v++) {
            float4 w = sv[v];
            float z = fmaf(w.x, ux, fmaf(w.y, uy, w.z * uz));
            float l = f_lg2(fmaxf(z, 1e-35f));
            lzv[v] = l;
            sum += f_ex2(pe * l);
        }
        float lg2h = ipe * f_lg2(sum);   // lg2 of h_out
        float ax = 0.0f, ay = 0.0f, az = 0.0f;
#pragma unroll
        for (int v = 0; v < Vc; v++) {
            float dh = f_ex2(pem1 * (lzv[v] - lg2h));
            dh = fminf(fmaxf(dh, 1e-30f), 1e30f);
            float4 w = sv[v];
            ax = fmaf(dh, w.x, ax);
            ay = fmaf(dh, w.y, ay);
            az = fmaf(dh, w.z, az);
        }
        int base = OFF_SURFP + (bp * Dc + d) * 3;
        out[base + 0] = ax + sconst[0];
        out[base + 1] = ay + sconst[1];
        out[base + 2] = az + sconst[2];
        g_nrml[(bp * Dc + d) * 3 + 0] = ux;
        g_nrml[(bp * Dc + d) * 3 + 1] = uy;
        g_nrml[(bp * Dc + d) * 3 + 2] = uz;
    }
}

// ---------------- mega kernel: 3x point-distance + surf_distance ----------------
// grid: (171, BPc).  x in [0,64): pc; [64,96): ns; [96,128): out; [128,171): sdist.
__global__ void __launch_bounds__(256, 4) k_mega(const float* __restrict__ pc,
                                                 const float* __restrict__ ns,
                                                 const float* __restrict__ op,
                                                 float* __restrict__ out) {
    __shared__ float4 sv[Vc];
    __shared__ float st[Pc * 3];
    __shared__ float sconst[5];   // tx,ty,tz,pe,ipe
    int bp  = blockIdx.y;
    int b   = bp >> 4;
    int tid = threadIdx.x;
    load_verts(sv, bp, tid);
    if (tid < Pc * 3) st[tid] = g_tr[b * Pc * 3 + tid];
    if (tid == 0) {
        sconst[0] = g_tr[bp * 3 + 0];
        sconst[1] = g_tr[bp * 3 + 1];
        sconst[2] = g_pe[bp];   // note: slot 2 reused below
        sconst[2] = g_tr[bp * 3 + 2];
        sconst[3] = g_pe[bp];
        sconst[4] = g_ipe[bp];
    }
    __syncthreads();

    int bx = blockIdx.x;
    if (bx < 128) {
        // ---- point-distance segments ----
        const float* pts; int N, outoff, q;
        if (bx < 64)       { pts = pc; N = NPCc;  outoff = OFF_DIST; q = bx * 256 + tid; }
        else if (bx < 96)  { pts = ns; N = NNSc;  outoff = OFF_NS;   q = (bx - 64) * 256 + tid; }
        else               { pts = op; N = NOUTc; outoff = OFF_OUT;  q = (bx - 96) * 256 + tid; }
        float px = pts[(b * N + q) * 3 + 0];
        float py = pts[(b * N + q) * 3 + 1];
        float pz = pts[(b * N + q) * 3 + 2];
        float lx = px - sconst[0];
        float ly = py - sconst[1];
        float lz = pz - sconst[2];
        float ss = lx * lx + ly * ly + lz * lz;
        ss = fminf(fmaxf(ss, 1e-40f), 1e40f);
        float rinv = f_rsqrt(ss);
        float nrm = ss * rinv;
        float ux = lx * rinv, uy = ly * rinv, uz = lz * rinv;
        float h = h_support(sv, sconst[3], sconst[4], ux, uy, uz);
        out[outoff + bp * N + q] = nrm - h;
        return;
    }

    // ---- surf_distance segment (with normal filter + diagonal) ----
    int n = (bx - 128) * 256 + tid;
    if (n >= PDc) return;
    int i  = bp & 15;
    int j  = n / Dc;
    int dd = n - j * Dc;

    float res = 100.0f;
    bool compute = (i != j);
    if (compute) {
        float nx = g_nrml[(bp * Dc + dd) * 3 + 0];
        float ny = g_nrml[(bp * Dc + dd) * 3 + 1];
        float nz = g_nrml[(bp * Dc + dd) * 3 + 2];
        float ltx = st[j * 3 + 0] - sconst[0];
        float lty = st[j * 3 + 1] - sconst[1];
        float ltz = st[j * 3 + 2] - sconst[2];
        float nf = ltx * nx + lty * ny + ltz * nz;
        compute = !(nf < 0.0f);
    }
    if (compute) {
        float px = out[OFF_SURFP + (b * PDc + n) * 3 + 0];
        float py = out[OFF_SURFP + (b * PDc + n) * 3 + 1];
        float pz = out[OFF_SURFP + (b * PDc + n) * 3 + 2];
        float lx = px - sconst[0];
        float ly = py - sconst[1];
        float lz = pz - sconst[2];
        float ss = lx * lx + ly * ly + lz * lz;
        ss = fminf(fmaxf(ss, 1e-40f), 1e40f);
        float rinv = f_rsqrt(ss);
        float nrm = ss * rinv;
        float ux = lx * rinv, uy = ly * rinv, uz = lz * rinv;
        float h = h_support(sv, sconst[3], sconst[4], ux, uy, uz);
        res = nrm - h;
    }
    out[OFF_SURFD + bp * PDc + n] = res;
}

// ---------------- launch ----------------
extern "C" void kernel_launch(void* const* d_in, const int* in_sizes, int n_in,
                              void* d_out, int out_size) {
    const float* verts  = (const float*)d_in[0];   // (B,P,V,3)
    const float* smooth = (const float*)d_in[1];   // (B,P)
    const float* pc     = (const float*)d_in[2];   // (B,NPC,3)
    const float* ns     = (const float*)d_in[3];   // (B,NNS,3)
    const float* op     = (const float*)d_in[4];   // (B,NOUT,3)
    float* out = (float*)d_out;

    k_init<<<19, 256>>>(verts, smooth);
    k_mid<<<Bc + BPc, 256>>>(out);
    k_mega<<<dim3(171, BPc), 256>>>(pc, ns, op, out);
    (void)in_sizes; (void)n_in; (void)out_size;
}

// round 17
// speedup vs baseline: 2.0764x; 1.0018x over previous
#include <cuda_runtime.h>
#include <math.h>

// ---------------- problem constants ----------------
#define Bc    8
#define Pc    16
#define Vc    32
#define Dc    686          // (20-2)*(39-1)+2
#define BPc   128          // B*P
#define NPCc  16384
#define NNSc  8192
#define NOUTc 8192
#define PDc   10976        // P*D

// ---------------- output offsets (tuple order, flattened) ----------------
#define OFF_OVERLAP 0                         // (B,P,P,1)     2048
#define OFF_DIST    2048                      // (B,P,NPC,1)   2097152
#define OFF_X       2099200                   // (B,P,D,3)     263424
#define OFF_SURFD   2362624                   // (B,P,P*D,1)   1404928
#define OFF_SURFP   3767552                   // (B,P*D,3)     263424
#define OFF_NS      4030976                   // (B,P,NNS,1)   1048576
#define OFF_OUT     5079552                   // (B,P,NOUT,1)  1048576
// total = 6128128

// ---------------- persistent device scratch ----------------
__device__ float  g_dirs[Dc * 3];
__device__ float  g_lv[BPc * 96];     // centered verts, [bp][coord(0..2)][v(0..31)]
__device__ float  g_tr[BPc * 3];      // mean (translation)
__device__ float  g_pe[BPc];
__device__ float  g_ipe[BPc];
__device__ float  g_nrml[BPc * Dc * 3];

// ---------------- fast approx helpers (single MUFU each) ----------------
__device__ __forceinline__ float f_rsqrt(float x) { float r; asm("rsqrt.approx.f32 %0, %1;" : "=f"(r) : "f"(x)); return r; }
__device__ __forceinline__ float f_lg2(float x)   { float r; asm("lg2.approx.f32 %0, %1;"   : "=f"(r) : "f"(x)); return r; }
__device__ __forceinline__ float f_ex2(float x)   { float r; asm("ex2.approx.f32 %0, %1;"   : "=f"(r) : "f"(x)); return r; }

// ---------------- core: UNNORMALIZED soft support ----------------
// Reference: h_out = zmax * (sum clip(max(z,0)/zmax)^pe)^(1/pe); the zmax
// normalization cancels algebraically and underflow semantics match in fp32.
__device__ __forceinline__ float h_support(
    const float4* __restrict__ sv, float pe, float ipe,
    float ux, float uy, float uz)
{
    float sum = 0.0f;
#pragma unroll
    for (int v = 0; v < Vc; v++) {
        float4 w = sv[v];
        float z  = fmaf(w.x, ux, fmaf(w.y, uy, w.z * uz));
        float lz = f_lg2(fmaxf(z, 1e-35f));
        sum += f_ex2(pe * lz);
    }
    return f_ex2(ipe * f_lg2(sum));   // sum==0 -> -inf -> 0, matches reference
}

// load one bp's vertex set into a float4 shared array (call with tid, then sync)
__device__ __forceinline__ void load_verts(float4* sv, int bp, int tid) {
    if (tid < Vc) {
        sv[tid] = make_float4(g_lv[bp * 96 +  0 + tid],
                              g_lv[bp * 96 + 32 + tid],
                              g_lv[bp * 96 + 64 + tid], 0.0f);
    }
}

// ---------------- kernel: init = dirs (spread over 22 one-warp blocks) + prep ----------------
// grid: 38 blocks x 256.  bid<22: dirs, one warp, idx=bid*32+lane (spreads FP64 trig
// across 22 SMs instead of 3).  bid>=22: prep, warp w handles bp=(bid-22)*8+w.
__global__ void __launch_bounds__(256) k_init(const float* __restrict__ verts,
                                              const float* __restrict__ smooth) {
    int tid = threadIdx.x;
    if (blockIdx.x < 22) {
        if (tid >= 32) return;
        int idx = blockIdx.x * 32 + tid;
        if (idx >= Dc) return;
        const double PI = 3.14159265358979323846;
        int i, j;
        if (idx < 684)      { i = idx / 38 + 1; j = idx % 38; }
        else if (idx == 684){ i = 0;  j = 0; }
        else                { i = 19; j = 0; }
        double th1 = (i == 19) ? (PI / 2.0) : (-PI / 2.0 + (PI / 19.0) * (double)i);
        double th2 = -PI + (PI / 19.0) * (double)j;
        double c1 = cos(th1), s1 = sin(th1);
        double c2 = cos(th2), s2 = sin(th2);
        g_dirs[idx * 3 + 0] = (float)(c1 * c2);
        g_dirs[idx * 3 + 1] = (float)(c1 * s2);
        g_dirs[idx * 3 + 2] = (float)s1;
        return;
    }
    int bp = (blockIdx.x - 22) * 8 + (tid >> 5);
    int v  = tid & 31;
    float x = verts[(bp * Vc + v) * 3 + 0];
    float y = verts[(bp * Vc + v) * 3 + 1];
    float z = verts[(bp * Vc + v) * 3 + 2];
    float sx = x, sy = y, sz = z;
#pragma unroll
    for (int o = 16; o; o >>= 1) {
        sx += __shfl_xor_sync(0xffffffffu, sx, o);
        sy += __shfl_xor_sync(0xffffffffu, sy, o);
        sz += __shfl_xor_sync(0xffffffffu, sz, o);
    }
    float mx = sx * (1.0f / 32.0f);
    float my = sy * (1.0f / 32.0f);
    float mz = sz * (1.0f / 32.0f);
    g_lv[bp * 96 +  0 + v] = x - mx;
    g_lv[bp * 96 + 32 + v] = y - my;
    g_lv[bp * 96 + 64 + v] = z - mz;
    if (v == 0) {
        g_tr[bp * 3 + 0] = mx;
        g_tr[bp * 3 + 1] = my;
        g_tr[bp * 3 + 2] = mz;
        float pe = smooth[bp];
        g_pe[bp]  = pe;
        g_ipe[bp] = 1.0f / pe;
    }
}

// ---------------- main kernel: overlap + supsurf + 3x point-distance ----------------
// 1D grid, 136 + 128*128 = 16520 blocks x 256 threads.
//   bid <   8:            overlap for batch bid
//   bid < 136:            support/x/scale + surface points/normals for bp=bid-8
//   else: t=bid-136, bp=t>>7, bx=t&127:
//         bx<64: pc dist; bx<96: ns dist; else: out dist
// Heavy per-bp blocks sit at low bid so they start in wave 1 and never straggle.
__global__ void __launch_bounds__(256, 4) k_main(const float* __restrict__ pc,
                                                 const float* __restrict__ ns,
                                                 const float* __restrict__ op,
                                                 float* __restrict__ out) {
    int tid = threadIdx.x;
    int bid = blockIdx.x;

    if (bid < Bc) {
        // ======== overlap (one block per batch) ========
        __shared__ float4 svb[Pc * Vc];
        __shared__ float stt[Pc * 3];
        __shared__ float spe[Pc], sipe[Pc];
        __shared__ float sh[Pc * Pc];
        int b = bid;
        {
            int p = tid >> 4, v2 = (tid & 15) * 2;
            svb[p * Vc + v2 + 0] = make_float4(g_lv[(b * Pc + p) * 96 +  0 + v2],
                                               g_lv[(b * Pc + p) * 96 + 32 + v2],
                                               g_lv[(b * Pc + p) * 96 + 64 + v2], 0.0f);
            svb[p * Vc + v2 + 1] = make_float4(g_lv[(b * Pc + p) * 96 +  0 + v2 + 1],
                                               g_lv[(b * Pc + p) * 96 + 32 + v2 + 1],
                                               g_lv[(b * Pc + p) * 96 + 64 + v2 + 1], 0.0f);
        }
        if (tid < Pc * 3) stt[tid] = g_tr[b * Pc * 3 + tid];
        if (tid < Pc) { spe[tid] = g_pe[b * Pc + tid]; sipe[tid] = g_ipe[b * Pc + tid]; }
        __syncthreads();

        int i = tid >> 4, j = tid & 15;
        float dx = stt[j * 3 + 0] - stt[i * 3 + 0];
        float dy = stt[j * 3 + 1] - stt[i * 3 + 1];
        float dz = stt[j * 3 + 2] - stt[i * 3 + 2];
        float ss = dx * dx + dy * dy + dz * dz;
        ss = fminf(fmaxf(ss, 1e-20f), 1e20f);
        float rinv = f_rsqrt(ss);
        float dn = ss * rinv;
        float ux, uy, uz;
        if (i == j) { ux = 1.0f; uy = 0.0f; uz = 0.0f; }
        else        { ux = dx * rinv; uy = dy * rinv; uz = dz * rinv; }

        sh[tid] = h_support(&svb[i * Vc], spe[i], sipe[i], ux, uy, uz);
        __syncthreads();

        float sep = dn - sh[i * 16 + j] - sh[j * 16 + i];
        float ov = fmaxf(-sep, 0.0f);
        if (i == j) ov = 0.0f;
        out[OFF_OVERLAP + b * 256 + i * 16 + j] = ov;
        return;
    }

    if (bid < Bc + BPc) {
        // ======== support (x, scale) + surface points/normals (one block per bp) ========
        __shared__ float4 sv[Vc];
        __shared__ float sconst[5];   // tx,ty,tz,pe,ipe
        __shared__ float red[8];
        __shared__ float s_scale;
        int bp = bid - Bc;
        load_verts(sv, bp, tid);
        if (tid == 0) {
            sconst[0] = g_tr[bp * 3 + 0];
            sconst[1] = g_tr[bp * 3 + 1];
            sconst[2] = g_tr[bp * 3 + 2];
            sconst[3] = g_pe[bp];
            sconst[4] = g_ipe[bp];
        }
        __syncthreads();

        float pe  = sconst[3];
        float ipe = sconst[4];

        // ---- phase 1: support along DIRS, write x, reduce scale ----
        float hmax = -1e30f;
        for (int d = tid; d < Dc; d += 256) {
            float ux = g_dirs[d * 3 + 0];
            float uy = g_dirs[d * 3 + 1];
            float uz = g_dirs[d * 3 + 2];
            hmax = fmaxf(hmax, h_support(sv, pe, ipe, ux, uy, uz));
            out[OFF_X + (bp * Dc + d) * 3 + 0] = ux;
            out[OFF_X + (bp * Dc + d) * 3 + 1] = uy;
            out[OFF_X + (bp * Dc + d) * 3 + 2] = uz;
        }
        float m = hmax;
#pragma unroll
        for (int o = 16; o; o >>= 1) m = fmaxf(m, __shfl_xor_sync(0xffffffffu, m, o));
        if ((tid & 31) == 0) red[tid >> 5] = m;
        __syncthreads();
        if (tid == 0) {
            float mm = red[0];
#pragma unroll
            for (int w = 1; w < 8; w++) mm = fmaxf(mm, red[w]);
            s_scale = fminf(fmaxf(mm, 1e-10f), 10.0f);
        }
        __syncthreads();

        // ---- phase 2: surface points + normals ----
        // dhdz = clip((z*k/h)^(pe-1)) = clip((z/h_out)^(pe-1))  (normalization cancels)
        float sc = s_scale;
        float pem1 = pe - 1.0f;
        for (int d = tid; d < Dc; d += 256) {
            float dxr = g_dirs[d * 3 + 0];
            float dyr = g_dirs[d * 3 + 1];
            float dzr = g_dirs[d * 3 + 2];
            // pts = dirs*scale + trans; local = pts - trans (replicate reference rounding)
            float px = dxr * sc + sconst[0];
            float py = dyr * sc + sconst[1];
            float pz = dzr * sc + sconst[2];
            float lx = px - sconst[0];
            float ly = py - sconst[1];
            float lz = pz - sconst[2];
            float ss = lx * lx + ly * ly + lz * lz;
            ss = fminf(fmaxf(ss, 1e-40f), 1e40f);
            float rinv = f_rsqrt(ss);
            float ux = lx * rinv, uy = ly * rinv, uz = lz * rinv;

            float lzv[Vc];
            float sum = 0.0f;
#pragma unroll
            for (int v = 0; v < Vc; v++) {
                float4 w = sv[v];
                float z = fmaf(w.x, ux, fmaf(w.y, uy, w.z * uz));
                float l = f_lg2(fmaxf(z, 1e-35f));
                lzv[v] = l;
                sum += f_ex2(pe * l);
            }
            float lg2h = ipe * f_lg2(sum);   // lg2 of h_out
            float ax = 0.0f, ay = 0.0f, az = 0.0f;
#pragma unroll
            for (int v = 0; v < Vc; v++) {
                float dh = f_ex2(pem1 * (lzv[v] - lg2h));
                dh = fminf(fmaxf(dh, 1e-30f), 1e30f);
                float4 w = sv[v];
                ax = fmaf(dh, w.x, ax);
                ay = fmaf(dh, w.y, ay);
                az = fmaf(dh, w.z, az);
            }
            int base = OFF_SURFP + (bp * Dc + d) * 3;
            out[base + 0] = ax + sconst[0];
            out[base + 1] = ay + sconst[1];
            out[base + 2] = az + sconst[2];
            g_nrml[(bp * Dc + d) * 3 + 0] = ux;
            g_nrml[(bp * Dc + d) * 3 + 1] = uy;
            g_nrml[(bp * Dc + d) * 3 + 2] = uz;
        }
        return;
    }

    // ======== point-distance segments ========
    __shared__ float4 sv[Vc];
    __shared__ float sconst[5];   // tx,ty,tz,pe,ipe
    int t  = bid - (Bc + BPc);
    int bp = t >> 7;
    int bx = t & 127;
    int b  = bp >> 4;
    load_verts(sv, bp, tid);
    if (tid == 0) {
        sconst[0] = g_tr[bp * 3 + 0];
        sconst[1] = g_tr[bp * 3 + 1];
        sconst[2] = g_tr[bp * 3 + 2];
        sconst[3] = g_pe[bp];
        sconst[4] = g_ipe[bp];
    }
    __syncthreads();

    const float* pts; int N, outoff, q;
    if (bx < 64)       { pts = pc; N = NPCc;  outoff = OFF_DIST; q = bx * 256 + tid; }
    else if (bx < 96)  { pts = ns; N = NNSc;  outoff = OFF_NS;   q = (bx - 64) * 256 + tid; }
    else               { pts = op; N = NOUTc; outoff = OFF_OUT;  q = (bx - 96) * 256 + tid; }
    float px = pts[(b * N + q) * 3 + 0];
    float py = pts[(b * N + q) * 3 + 1];
    float pz = pts[(b * N + q) * 3 + 2];
    float lx = px - sconst[0];
    float ly = py - sconst[1];
    float lz = pz - sconst[2];
    float ss = lx * lx + ly * ly + lz * lz;
    ss = fminf(fmaxf(ss, 1e-40f), 1e40f);
    float rinv = f_rsqrt(ss);
    float nrm = ss * rinv;
    float ux = lx * rinv, uy = ly * rinv, uz = lz * rinv;
    float h = h_support(sv, sconst[3], sconst[4], ux, uy, uz);
    out[outoff + bp * N + q] = nrm - h;
}

// ---------------- kernel: surf_distance (normal filter + diagonal) ----------------
// grid: (43, BPc) x 256
__global__ void __launch_bounds__(256, 4) k_sdist(float* __restrict__ out) {
    __shared__ float4 sv[Vc];
    __shared__ float stt[Pc * 3];
    __shared__ float sconst[5];   // tx,ty,tz,pe,ipe
    int bp  = blockIdx.y;
    int b   = bp >> 4;
    int tid = threadIdx.x;
    load_verts(sv, bp, tid);
    if (tid < Pc * 3) stt[tid] = g_tr[b * Pc * 3 + tid];
    if (tid == 0) {
        sconst[0] = g_tr[bp * 3 + 0];
        sconst[1] = g_tr[bp * 3 + 1];
        sconst[2] = g_tr[bp * 3 + 2];
        sconst[3] = g_pe[bp];
        sconst[4] = g_ipe[bp];
    }
    __syncthreads();

    int n = blockIdx.x * 256 + tid;
    if (n >= PDc) return;
    int i  = bp & 15;
    int j  = n / Dc;
    int dd = n - j * Dc;

    float res = 100.0f;
    bool compute = (i != j);
    if (compute) {
        float nx = g_nrml[(bp * Dc + dd) * 3 + 0];
        float ny = g_nrml[(bp * Dc + dd) * 3 + 1];
        float nz = g_nrml[(bp * Dc + dd) * 3 + 2];
        float ltx = stt[j * 3 + 0] - sconst[0];
        float lty = stt[j * 3 + 1] - sconst[1];
        float ltz = stt[j * 3 + 2] - sconst[2];
        float nf = ltx * nx + lty * ny + ltz * nz;
        compute = !(nf < 0.0f);
    }
    if (compute) {
        float px = out[OFF_SURFP + (b * PDc + n) * 3 + 0];
        float py = out[OFF_SURFP + (b * PDc + n) * 3 + 1];
        float pz = out[OFF_SURFP + (b * PDc + n) * 3 + 2];
        float lx = px - sconst[0];
        float ly = py - sconst[1];
        float lz = pz - sconst[2];
        float ss = lx * lx + ly * ly + lz * lz;
        ss = fminf(fmaxf(ss, 1e-40f), 1e40f);
        float rinv = f_rsqrt(ss);
        float nrm = ss * rinv;
        float ux = lx * rinv, uy = ly * rinv, uz = lz * rinv;
        float h = h_support(sv, sconst[3], sconst[4], ux, uy, uz);
        res = nrm - h;
    }
    out[OFF_SURFD + bp * PDc + n] = res;
}

// ---------------- launch ----------------
extern "C" void kernel_launch(void* const* d_in, const int* in_sizes, int n_in,
                              void* d_out, int out_size) {
    const float* verts  = (const float*)d_in[0];   // (B,P,V,3)
    const float* smooth = (const float*)d_in[1];   // (B,P)
    const float* pc     = (const float*)d_in[2];   // (B,NPC,3)
    const float* ns     = (const float*)d_in[3];   // (B,NNS,3)
    const float* op     = (const float*)d_in[4];   // (B,NOUT,3)
    float* out = (float*)d_out;

    k_init<<<38, 256>>>(verts, smooth);
    k_main<<<Bc + BPc + BPc * 128, 256>>>(pc, ns, op, out);
    k_sdist<<<dim3(43, BPc), 256>>>(out);
    (void)in_sizes; (void)n_in; (void)out_size;
}